// round 1
// baseline (speedup 1.0000x reference)
#include <cuda_runtime.h>

// SEIR scan: B independent channels, sequential over T.
// Output layout: [4, T, B] — planes S, E, I, R.

#define THREADS 64

__global__ __launch_bounds__(THREADS, 1)
void seir_scan_kernel(const float* __restrict__ X,
                      const float* __restrict__ w_beta,
                      const float* __restrict__ w_gamma,
                      const float* __restrict__ w_sigma,
                      const float* __restrict__ S0,
                      const float* __restrict__ I0,
                      const float* __restrict__ R0,
                      const float* __restrict__ Nvec,
                      float* __restrict__ out,
                      int T, int B)
{
    const int b = blockIdx.x * blockDim.x + threadIdx.x;
    if (b >= B) return;

    const float wb   = w_beta[b];
    const float wg   = w_gamma[b];
    const float ws   = w_sigma[b];
    const float invN = 1.0f / Nvec[b];

    float S = S0[b];
    float E = 0.0f;
    float I = I0[b];
    float R = R0[b];

    const long long TB = (long long)T * (long long)B;
    float* __restrict__ outS = out;
    float* __restrict__ outE = out + TB;
    float* __restrict__ outI = out + 2 * TB;
    float* __restrict__ outR = out + 3 * TB;

    // t = 0 row: initial state
    outS[b] = S;
    outE[b] = 0.0f;
    outI[b] = I;
    outR[b] = R;

    const int NSTEP = T - 1;   // steps use X[0..T-2], write rows 1..T-1

    // 4-deep prefetch ring for X to keep DRAM loads in flight.
    float x0 = (0 < NSTEP) ? X[(long long)0 * B + b] : 0.0f;
    float x1 = (1 < NSTEP) ? X[(long long)1 * B + b] : 0.0f;
    float x2 = (2 < NSTEP) ? X[(long long)2 * B + b] : 0.0f;
    float x3 = (3 < NSTEP) ? X[(long long)3 * B + b] : 0.0f;

    int t = 0;
    // Main chunks of 4 (fully unrolled, prefetch next 4 at chunk head).
    for (; t + 4 <= NSTEP; t += 4) {
        float n0 = 0.f, n1 = 0.f, n2 = 0.f, n3 = 0.f;
        const int tn = t + 4;
        if (tn + 0 < NSTEP) n0 = X[(long long)(tn + 0) * B + b];
        if (tn + 1 < NSTEP) n1 = X[(long long)(tn + 1) * B + b];
        if (tn + 2 < NSTEP) n2 = X[(long long)(tn + 2) * B + b];
        if (tn + 3 < NSTEP) n3 = X[(long long)(tn + 3) * B + b];

        #pragma unroll
        for (int k = 0; k < 4; ++k) {
            const float x = (k == 0) ? x0 : (k == 1) ? x1 : (k == 2) ? x2 : x3;
            const float beta  = x * wb;
            const float gamma = x * wg;
            const float sigma = x * ws;
            const float StoE  = beta * I * S * invN;
            const float EtoI  = sigma * E;
            const float ItoR  = gamma * I;
            S = S - StoE;
            E = E + StoE - EtoI;
            I = I + EtoI - ItoR;
            R = R + ItoR;
            const long long row = (long long)(t + k + 1) * B + b;
            outS[row] = S;
            outE[row] = E;
            outI[row] = I;
            outR[row] = R;
        }
        x0 = n0; x1 = n1; x2 = n2; x3 = n3;
    }

    // Tail (NSTEP % 4 iterations).
    for (; t < NSTEP; ++t) {
        const float x = (t == ((NSTEP / 4) * 4)) ? x0
                      : (t == ((NSTEP / 4) * 4) + 1) ? x1 : x2;
        const float beta  = x * wb;
        const float gamma = x * wg;
        const float sigma = x * ws;
        const float StoE  = beta * I * S * invN;
        const float EtoI  = sigma * E;
        const float ItoR  = gamma * I;
        S = S - StoE;
        E = E + StoE - EtoI;
        I = I + EtoI - ItoR;
        R = R + ItoR;
        const long long row = (long long)(t + 1) * B + b;
        outS[row] = S;
        outE[row] = E;
        outI[row] = I;
        outR[row] = R;
    }
}

extern "C" void kernel_launch(void* const* d_in, const int* in_sizes, int n_in,
                              void* d_out, int out_size)
{
    const float* X      = (const float*)d_in[0];
    const float* w_beta = (const float*)d_in[1];
    const float* w_gamma= (const float*)d_in[2];
    const float* w_sigma= (const float*)d_in[3];
    const float* S0     = (const float*)d_in[4];
    const float* I0     = (const float*)d_in[5];
    const float* R0     = (const float*)d_in[6];
    const float* Nvec   = (const float*)d_in[7];
    float* out = (float*)d_out;

    const int B = in_sizes[1];            // w_beta is [B]
    const int T = in_sizes[0] / B;        // X is [T, B]

    const int grid = (B + THREADS - 1) / THREADS;
    seir_scan_kernel<<<grid, THREADS>>>(X, w_beta, w_gamma, w_sigma,
                                        S0, I0, R0, Nvec, out, T, B);
}

// round 2
// speedup vs baseline: 2.2991x; 2.2991x over previous
#include <cuda_runtime.h>

// SEIR scan, two-pass chunked recomputation.
// Output layout: [4, T, B] — planes S, E, I, R.
//
// Pass 1: one thread per channel, serial scan over T, saves state every
//         STEP steps into __device__ scratch (no bulk output).
// Pass 2: (chunk, channel/4) threads, each recomputes its 32-step chunk
//         from the saved boundary and writes the output with float4 stores.

#define STEP   32
#define MAXB   8192
#define MAXC   80   // supports T up to 2560

__device__ float g_bS[MAXC * MAXB];
__device__ float g_bE[MAXC * MAXB];
__device__ float g_bI[MAXC * MAXB];
__device__ float g_bR[MAXC * MAXB];

__device__ __forceinline__ void seir_step(float x, float wb, float wg, float ws,
                                          float invN,
                                          float& S, float& E, float& I, float& R)
{
    const float beta  = x * wb;
    const float gamma = x * wg;
    const float sigma = x * ws;
    const float StoE  = beta * I * S * invN;
    const float EtoI  = sigma * E;
    const float ItoR  = gamma * I;
    S = S - StoE;
    E = E + StoE - EtoI;
    I = I + EtoI - ItoR;
    R = R + ItoR;
}

// ---------------------------------------------------------------- pass 1
__global__ __launch_bounds__(64, 1)
void seir_pass1(const float* __restrict__ X,
                const float* __restrict__ w_beta,
                const float* __restrict__ w_gamma,
                const float* __restrict__ w_sigma,
                const float* __restrict__ S0,
                const float* __restrict__ I0,
                const float* __restrict__ R0,
                const float* __restrict__ Nvec,
                int T, int B, int chunks)
{
    const int b = blockIdx.x * blockDim.x + threadIdx.x;
    if (b >= B) return;

    const float wb   = w_beta[b];
    const float wg   = w_gamma[b];
    const float ws   = w_sigma[b];
    const float invN = 1.0f / Nvec[b];

    float S = S0[b];
    float E = 0.0f;
    float I = I0[b];
    float R = R0[b];

    // chunk 0 boundary = initial state
    g_bS[b] = S; g_bE[b] = E; g_bI[b] = I; g_bR[b] = R;

    const int NS = (chunks - 1) * STEP;   // scan far enough for last boundary

    // 32-deep register prefetch ring: distance ≈ 32 iters ≈ 512 cyc,
    // covering DRAM latency.
    float xr[STEP];
#pragma unroll
    for (int k = 0; k < STEP; ++k)
        xr[k] = (k < NS) ? X[(size_t)k * B + b] : 0.0f;

    for (int base = 0; base < NS; base += STEP) {
#pragma unroll
        for (int k = 0; k < STEP; ++k) {
            const float x = xr[k];
            const int tn = base + STEP + k;
            xr[k] = (tn < NS) ? X[(size_t)tn * B + b] : 0.0f;
            seir_step(x, wb, wg, ws, invN, S, E, I, R);
        }
        const int c = (base / STEP) + 1;
        const size_t idx = (size_t)c * B + b;
        g_bS[idx] = S; g_bE[idx] = E; g_bI[idx] = I; g_bR[idx] = R;
    }
}

// ---------------------------------------------------------------- pass 2
__global__ __launch_bounds__(256)
void seir_pass2(const float* __restrict__ X,
                const float* __restrict__ w_beta,
                const float* __restrict__ w_gamma,
                const float* __restrict__ w_sigma,
                float* __restrict__ out,
                int T, int B)
{
    const int j = blockIdx.x * blockDim.x + threadIdx.x;  // channel group
    const int b = j * 4;
    if (b >= B) return;

    const int c  = blockIdx.y;
    const int t0 = c * STEP;
    if (t0 >= T) return;
    const int tend = min(t0 + STEP, T);
    const int nst  = tend - t0 - 1;   // steps inside this chunk

    const float4 wb = *(const float4*)(w_beta  + b);
    const float4 wg = *(const float4*)(w_gamma + b);
    const float4 ws = *(const float4*)(w_sigma + b);

    const size_t bi = (size_t)c * B + b;
    float4 S = *(const float4*)(g_bS + bi);
    float4 E = *(const float4*)(g_bE + bi);
    float4 I = *(const float4*)(g_bI + bi);
    float4 R = *(const float4*)(g_bR + bi);

    const size_t TB = (size_t)T * (size_t)B;
    float* __restrict__ oS = out;
    float* __restrict__ oE = out + TB;
    float* __restrict__ oI = out + 2 * TB;
    float* __restrict__ oR = out + 3 * TB;

    // write boundary row t0
    size_t r = (size_t)t0 * B + b;
    *(float4*)(oS + r) = S;
    *(float4*)(oE + r) = E;
    *(float4*)(oI + r) = I;
    *(float4*)(oR + r) = R;

    const float* xp = X + (size_t)t0 * B + b;
    float4 xn = (nst > 0) ? *(const float4*)xp : make_float4(0.f, 0.f, 0.f, 0.f);

#pragma unroll 4
    for (int i = 0; i < nst; ++i) {
        const float4 x = xn;
        if (i + 1 < nst)
            xn = *(const float4*)(xp + (size_t)(i + 1) * B);

        seir_step(x.x, wb.x, wg.x, ws.x, 1.0f, S.x, E.x, I.x, R.x);
        seir_step(x.y, wb.y, wg.y, ws.y, 1.0f, S.y, E.y, I.y, R.y);
        seir_step(x.z, wb.z, wg.z, ws.z, 1.0f, S.z, E.z, I.z, R.z);
        seir_step(x.w, wb.w, wg.w, ws.w, 1.0f, S.w, E.w, I.w, R.w);

        r += B;
        *(float4*)(oS + r) = S;
        *(float4*)(oE + r) = E;
        *(float4*)(oI + r) = I;
        *(float4*)(oR + r) = R;
    }
}

// N == 1 in this dataset, but keep correctness for general N: pass 2 above
// uses invN = 1.  To stay correct for arbitrary N we fold 1/N into w_beta
// cannot do (w_beta reused).  Instead pass invN per lane:
__global__ __launch_bounds__(256)
void seir_pass2_gen(const float* __restrict__ X,
                    const float* __restrict__ w_beta,
                    const float* __restrict__ w_gamma,
                    const float* __restrict__ w_sigma,
                    const float* __restrict__ Nvec,
                    float* __restrict__ out,
                    int T, int B)
{
    const int j = blockIdx.x * blockDim.x + threadIdx.x;
    const int b = j * 4;
    if (b >= B) return;

    const int c  = blockIdx.y;
    const int t0 = c * STEP;
    if (t0 >= T) return;
    const int tend = min(t0 + STEP, T);
    const int nst  = tend - t0 - 1;

    const float4 wb = *(const float4*)(w_beta  + b);
    const float4 wg = *(const float4*)(w_gamma + b);
    const float4 ws = *(const float4*)(w_sigma + b);
    const float4 nv = *(const float4*)(Nvec    + b);
    const float4 invN = make_float4(1.0f / nv.x, 1.0f / nv.y,
                                    1.0f / nv.z, 1.0f / nv.w);

    const size_t bi = (size_t)c * B + b;
    float4 S = *(const float4*)(g_bS + bi);
    float4 E = *(const float4*)(g_bE + bi);
    float4 I = *(const float4*)(g_bI + bi);
    float4 R = *(const float4*)(g_bR + bi);

    const size_t TB = (size_t)T * (size_t)B;
    float* __restrict__ oS = out;
    float* __restrict__ oE = out + TB;
    float* __restrict__ oI = out + 2 * TB;
    float* __restrict__ oR = out + 3 * TB;

    size_t r = (size_t)t0 * B + b;
    *(float4*)(oS + r) = S;
    *(float4*)(oE + r) = E;
    *(float4*)(oI + r) = I;
    *(float4*)(oR + r) = R;

    const float* xp = X + (size_t)t0 * B + b;
    float4 xn = (nst > 0) ? *(const float4*)xp : make_float4(0.f, 0.f, 0.f, 0.f);

#pragma unroll 4
    for (int i = 0; i < nst; ++i) {
        const float4 x = xn;
        if (i + 1 < nst)
            xn = *(const float4*)(xp + (size_t)(i + 1) * B);

        seir_step(x.x, wb.x, wg.x, ws.x, invN.x, S.x, E.x, I.x, R.x);
        seir_step(x.y, wb.y, wg.y, ws.y, invN.y, S.y, E.y, I.y, R.y);
        seir_step(x.z, wb.z, wg.z, ws.z, invN.z, S.z, E.z, I.z, R.z);
        seir_step(x.w, wb.w, wg.w, ws.w, invN.w, S.w, E.w, I.w, R.w);

        r += B;
        *(float4*)(oS + r) = S;
        *(float4*)(oE + r) = E;
        *(float4*)(oI + r) = I;
        *(float4*)(oR + r) = R;
    }
}

// ------------------------------------------------ fallback (shape safety)
__global__ void seir_fallback(const float* __restrict__ X,
                              const float* __restrict__ w_beta,
                              const float* __restrict__ w_gamma,
                              const float* __restrict__ w_sigma,
                              const float* __restrict__ S0,
                              const float* __restrict__ I0,
                              const float* __restrict__ R0,
                              const float* __restrict__ Nvec,
                              float* __restrict__ out, int T, int B)
{
    const int b = blockIdx.x * blockDim.x + threadIdx.x;
    if (b >= B) return;
    const float wb = w_beta[b], wg = w_gamma[b], ws = w_sigma[b];
    const float invN = 1.0f / Nvec[b];
    float S = S0[b], E = 0.0f, I = I0[b], R = R0[b];
    const size_t TB = (size_t)T * B;
    out[b] = S; out[TB + b] = E; out[2 * TB + b] = I; out[3 * TB + b] = R;
    for (int t = 0; t < T - 1; ++t) {
        const float x = X[(size_t)t * B + b];
        seir_step(x, wb, wg, ws, invN, S, E, I, R);
        const size_t r = (size_t)(t + 1) * B + b;
        out[r] = S; out[TB + r] = E; out[2 * TB + r] = I; out[3 * TB + r] = R;
    }
}

extern "C" void kernel_launch(void* const* d_in, const int* in_sizes, int n_in,
                              void* d_out, int out_size)
{
    const float* X      = (const float*)d_in[0];
    const float* w_beta = (const float*)d_in[1];
    const float* w_gamma= (const float*)d_in[2];
    const float* w_sigma= (const float*)d_in[3];
    const float* S0     = (const float*)d_in[4];
    const float* I0     = (const float*)d_in[5];
    const float* R0     = (const float*)d_in[6];
    const float* Nvec   = (const float*)d_in[7];
    float* out = (float*)d_out;

    const int B = in_sizes[1];         // w_beta is [B]
    const int T = in_sizes[0] / B;     // X is [T, B]
    const int chunks = (T + STEP - 1) / STEP;

    if (B <= MAXB && (B % 4) == 0 && chunks <= MAXC && T >= 2) {
        seir_pass1<<<(B + 63) / 64, 64>>>(X, w_beta, w_gamma, w_sigma,
                                          S0, I0, R0, Nvec, T, B, chunks);
        dim3 g2((B / 4 + 255) / 256, chunks);
        seir_pass2_gen<<<g2, 256>>>(X, w_beta, w_gamma, w_sigma, Nvec,
                                    out, T, B);
    } else {
        seir_fallback<<<(B + 127) / 128, 128>>>(X, w_beta, w_gamma, w_sigma,
                                                S0, I0, R0, Nvec, out, T, B);
    }
}

// round 3
// speedup vs baseline: 3.0458x; 1.3247x over previous
#include <cuda_runtime.h>

// SEIR scan, two-pass chunked recomputation.
// Output layout: [4, T, B] — planes S, E, I, R.
//
// Pass 1: one thread per channel, lean serial scan, 48-deep register
//         prefetch ring, boundary state saved every STEP steps.
// Pass 2: (chunk, channel/4) grid, recomputes 16-step chunks, float4
//         streaming stores.

#define STEP   16
#define RING   48
#define MAXB   8192
#define MAXC   256   // supports T up to 4096

__device__ float g_bS[MAXC * MAXB];
__device__ float g_bE[MAXC * MAXB];
__device__ float g_bI[MAXC * MAXB];
__device__ float g_bR[MAXC * MAXB];

// one SEIR step; invN already folded into wbN
__device__ __forceinline__ void seir_step(float x, float wbN, float wg, float ws,
                                          float& S, float& E, float& I, float& R)
{
    const float t1   = x * wbN;
    const float t2   = x * ws;
    const float t3   = x * wg;
    const float StoE = t1 * I * S;
    const float EtoI = t2 * E;
    const float ItoR = t3 * I;
    S = S - StoE;
    E = E + (StoE - EtoI);
    I = I + (EtoI - ItoR);
    R = R + ItoR;
}

// ---------------------------------------------------------------- pass 1
__global__ __launch_bounds__(64, 1)
void seir_pass1(const float* __restrict__ X,
                const float* __restrict__ w_beta,
                const float* __restrict__ w_gamma,
                const float* __restrict__ w_sigma,
                const float* __restrict__ S0,
                const float* __restrict__ I0,
                const float* __restrict__ R0,
                const float* __restrict__ Nvec,
                int B, int NS)   // NS = (chunks-1)*STEP serial steps
{
    const int b = blockIdx.x * blockDim.x + threadIdx.x;
    if (b >= B) return;

    const float invN = 1.0f / Nvec[b];
    const float wbN  = w_beta[b] * invN;
    const float wg   = w_gamma[b];
    const float ws   = w_sigma[b];

    float S = S0[b];
    float E = 0.0f;
    float I = I0[b];
    float R = R0[b];

    // boundary 0 = initial state
    g_bS[b] = S; g_bE[b] = E; g_bI[b] = I; g_bR[b] = R;

    const float* __restrict__ xp = X + b;

    // prologue: fill ring (predicated; runs once)
    float xr[RING];
#pragma unroll
    for (int k = 0; k < RING; ++k)
        xr[k] = (k < NS) ? xp[k * B] : 0.0f;

    int base = 0;

    // main: full chunks with UNPREDICATED prefetch of the next full chunk
    for (; base + 2 * RING <= NS; base += RING) {
        const float* __restrict__ pf = xp + (base + RING) * B;
#pragma unroll
        for (int k = 0; k < RING; ++k) {
            const float x = xr[k];
            xr[k] = pf[k * B];
            seir_step(x, wbN, wg, ws, S, E, I, R);
            if (((k + 1) & (STEP - 1)) == 0) {      // static: k = 15, 31, 47
                const int c = (base + k + 1) / STEP;
                const int idx = c * B + b;
                g_bS[idx] = S; g_bE[idx] = E; g_bI[idx] = I; g_bR[idx] = R;
            }
        }
    }

    // tail: predicated consume / prefetch (≤ 2*RING steps)
    for (; base < NS; base += RING) {
#pragma unroll
        for (int k = 0; k < RING; ++k) {
            const int t = base + k;
            if (t < NS) {
                const float x = xr[k];
                const int tn = t + RING;
                xr[k] = (tn < NS) ? xp[tn * B] : 0.0f;
                seir_step(x, wbN, wg, ws, S, E, I, R);
                if (((t + 1) % STEP) == 0) {
                    const int c = (t + 1) / STEP;
                    const int idx = c * B + b;
                    g_bS[idx] = S; g_bE[idx] = E; g_bI[idx] = I; g_bR[idx] = R;
                }
            }
        }
    }
}

// ---------------------------------------------------------------- pass 2
__global__ __launch_bounds__(256)
void seir_pass2(const float* __restrict__ X,
                const float* __restrict__ w_beta,
                const float* __restrict__ w_gamma,
                const float* __restrict__ w_sigma,
                const float* __restrict__ Nvec,
                float* __restrict__ out,
                int T, int B)
{
    const int j = blockIdx.x * blockDim.x + threadIdx.x;  // channel/4
    const int b = j * 4;
    if (b >= B) return;

    const int c  = blockIdx.y;
    const int t0 = c * STEP;
    if (t0 >= T) return;
    const int tend = min(t0 + STEP, T);
    const int nst  = tend - t0 - 1;

    const float4 wb = *(const float4*)(w_beta  + b);
    const float4 wg = *(const float4*)(w_gamma + b);
    const float4 ws = *(const float4*)(w_sigma + b);
    const float4 nv = *(const float4*)(Nvec    + b);
    const float4 wbN = make_float4(wb.x / nv.x, wb.y / nv.y,
                                   wb.z / nv.z, wb.w / nv.w);

    const int bi = c * B + b;
    float4 S = *(const float4*)(g_bS + bi);
    float4 E = *(const float4*)(g_bE + bi);
    float4 I = *(const float4*)(g_bI + bi);
    float4 R = *(const float4*)(g_bR + bi);

    const size_t TB = (size_t)T * (size_t)B;
    float* __restrict__ oS = out;
    float* __restrict__ oE = out + TB;
    float* __restrict__ oI = out + 2 * TB;
    float* __restrict__ oR = out + 3 * TB;

    // boundary row t0 (streaming stores: output is never re-read)
    size_t r = (size_t)t0 * B + b;
    __stcs((float4*)(oS + r), S);
    __stcs((float4*)(oE + r), E);
    __stcs((float4*)(oI + r), I);
    __stcs((float4*)(oR + r), R);

    const float* __restrict__ xp = X + (size_t)t0 * B + b;
    float4 xn = (nst > 0) ? *(const float4*)xp : make_float4(0.f, 0.f, 0.f, 0.f);

    if (nst == STEP - 1) {
        // common fully-unrolled path
#pragma unroll
        for (int i = 0; i < STEP - 1; ++i) {
            const float4 x = xn;
            if (i + 1 < STEP - 1)
                xn = *(const float4*)(xp + (i + 1) * B);

            seir_step(x.x, wbN.x, wg.x, ws.x, S.x, E.x, I.x, R.x);
            seir_step(x.y, wbN.y, wg.y, ws.y, S.y, E.y, I.y, R.y);
            seir_step(x.z, wbN.z, wg.z, ws.z, S.z, E.z, I.z, R.z);
            seir_step(x.w, wbN.w, wg.w, ws.w, S.w, E.w, I.w, R.w);

            r += B;
            __stcs((float4*)(oS + r), S);
            __stcs((float4*)(oE + r), E);
            __stcs((float4*)(oI + r), I);
            __stcs((float4*)(oR + r), R);
        }
    } else {
        for (int i = 0; i < nst; ++i) {
            const float4 x = xn;
            if (i + 1 < nst)
                xn = *(const float4*)(xp + (i + 1) * B);

            seir_step(x.x, wbN.x, wg.x, ws.x, S.x, E.x, I.x, R.x);
            seir_step(x.y, wbN.y, wg.y, ws.y, S.y, E.y, I.y, R.y);
            seir_step(x.z, wbN.z, wg.z, ws.z, S.z, E.z, I.z, R.z);
            seir_step(x.w, wbN.w, wg.w, ws.w, S.w, E.w, I.w, R.w);

            r += B;
            __stcs((float4*)(oS + r), S);
            __stcs((float4*)(oE + r), E);
            __stcs((float4*)(oI + r), I);
            __stcs((float4*)(oR + r), R);
        }
    }
}

// ------------------------------------------------ fallback (shape safety)
__global__ void seir_fallback(const float* __restrict__ X,
                              const float* __restrict__ w_beta,
                              const float* __restrict__ w_gamma,
                              const float* __restrict__ w_sigma,
                              const float* __restrict__ S0,
                              const float* __restrict__ I0,
                              const float* __restrict__ R0,
                              const float* __restrict__ Nvec,
                              float* __restrict__ out, int T, int B)
{
    const int b = blockIdx.x * blockDim.x + threadIdx.x;
    if (b >= B) return;
    const float invN = 1.0f / Nvec[b];
    const float wbN = w_beta[b] * invN;
    const float wg = w_gamma[b], ws = w_sigma[b];
    float S = S0[b], E = 0.0f, I = I0[b], R = R0[b];
    const size_t TB = (size_t)T * B;
    out[b] = S; out[TB + b] = E; out[2 * TB + b] = I; out[3 * TB + b] = R;
    for (int t = 0; t < T - 1; ++t) {
        const float x = X[(size_t)t * B + b];
        seir_step(x, wbN, wg, ws, S, E, I, R);
        const size_t r = (size_t)(t + 1) * B + b;
        out[r] = S; out[TB + r] = E; out[2 * TB + r] = I; out[3 * TB + r] = R;
    }
}

extern "C" void kernel_launch(void* const* d_in, const int* in_sizes, int n_in,
                              void* d_out, int out_size)
{
    const float* X      = (const float*)d_in[0];
    const float* w_beta = (const float*)d_in[1];
    const float* w_gamma= (const float*)d_in[2];
    const float* w_sigma= (const float*)d_in[3];
    const float* S0     = (const float*)d_in[4];
    const float* I0     = (const float*)d_in[5];
    const float* R0     = (const float*)d_in[6];
    const float* Nvec   = (const float*)d_in[7];
    float* out = (float*)d_out;

    const int B = in_sizes[1];         // w_beta is [B]
    const int T = in_sizes[0] / B;     // X is [T, B]
    const int chunks = (T + STEP - 1) / STEP;

    if (B <= MAXB && (B % 4) == 0 && chunks <= MAXC && T >= 2) {
        const int NS = (chunks - 1) * STEP;
        seir_pass1<<<(B + 63) / 64, 64>>>(X, w_beta, w_gamma, w_sigma,
                                          S0, I0, R0, Nvec, B, NS);
        dim3 g2((B / 4 + 255) / 256, chunks);
        seir_pass2<<<g2, 256>>>(X, w_beta, w_gamma, w_sigma, Nvec,
                                out, T, B);
    } else {
        seir_fallback<<<(B + 127) / 128, 128>>>(X, w_beta, w_gamma, w_sigma,
                                                S0, I0, R0, Nvec, out, T, B);
    }
}